// round 6
// baseline (speedup 1.0000x reference)
#include <cuda_runtime.h>
#include <math.h>

#define FULLM 0xffffffffu
static const int NMAX = 100352;
static const int EMAX = 1700000;

// ---------------- device scratch ----------------
__device__ long long d_musum[256];
__device__ int      d_cnt[NMAX];
__device__ int      d_cur[NMAX];
__device__ int      d_off[NMAX + 1];
__device__ float    d_dinv[NMAX];
__device__ int      d_col[EMAX];
__device__ unsigned d_bits0[NMAX * 8];
__device__ unsigned d_bits1[NMAX * 4];
__device__ unsigned d_bits2[NMAX * 4];
__device__ int      d_g8[NMAX * 32];        // packed int8 cnt/2 (exact)
__device__ unsigned d_wb0[8 * 128];
__device__ unsigned d_wb1[4 * 128];
__device__ unsigned d_wb2[4 * 40];
__device__ __align__(16) float d_al0[128];
__device__ __align__(16) float d_al1[128];
__device__ __align__(16) float d_al2[40];

__device__ __forceinline__ int detect64(const void* e) {
    const unsigned* w = (const unsigned*)e;
    int lane = threadIdx.x & 31;
    unsigned h0 = w[2 * lane + 1];
    unsigned h1 = w[64 + 2 * lane + 1];
    int z = __popc(__ballot_sync(FULLM, h0 == 0)) + __popc(__ballot_sync(FULLM, h1 == 0));
    return z >= 32;
}
__device__ __forceinline__ int ld_edge(const void* e, long long idx, int is64) {
    return is64 ? (int)((const long long*)e)[idx] : ((const int*)e)[idx];
}

// ============ L1: colsum partial (int64 atomics) | wprep | degree histogram ============
__global__ void k_prep(const float* __restrict__ x,
                       const float* __restrict__ W0,
                       const float* __restrict__ W1,
                       const float* __restrict__ W2,
                       const void* __restrict__ e, long long E, int n) {
    int bid = blockIdx.x;
    if (bid < 512) {
        int rows = (n + 511) / 512;
        int r0 = bid * rows, r1 = min(n, r0 + rows);
        float s = 0.f;
        for (int r = r0; r < r1; r++) s += x[(long long)r * 256 + threadIdx.x];
        long long q = llrintf(s * 4194304.f);   // 2^22 fixed point, deterministic sum
        atomicAdd((unsigned long long*)&d_musum[threadIdx.x], (unsigned long long)q);
    } else if (bid < 549) {
        int W = (bid - 512) * 8 + (threadIdx.x >> 5);
        int lane = threadIdx.x & 31;
        const float* Wsrc; unsigned* wbT; float* alpha; int K, OUT, j;
        if (W < 128)      { Wsrc = W0; wbT = d_wb0; alpha = d_al0; K = 256; OUT = 128; j = W; }
        else if (W < 256) { Wsrc = W1; wbT = d_wb1; alpha = d_al1; K = 128; OUT = 128; j = W - 128; }
        else if (W < 296) { Wsrc = W2; wbT = d_wb2; alpha = d_al2; K = 128; OUT = 40;  j = W - 256; }
        else return;
        float s = 0.f;
        int KW = K / 32;
        for (int w = 0; w < KW; w++) {
            float v = Wsrc[(long long)(w * 32 + lane) * OUT + j];
            s += fabsf(v);
            unsigned m = __ballot_sync(FULLM, v > 0.f);
            if (lane == 0) wbT[w * OUT + j] = m;
        }
        for (int o = 16; o; o >>= 1) s += __shfl_xor_sync(FULLM, s, o);
        if (lane == 0) alpha[j] = s / (float)K;
    } else {
        int is64 = detect64(e);
        long long i = (long long)(bid - 549) * blockDim.x + threadIdx.x;
        if (i < E) atomicAdd(&d_cnt[ld_edge(e, E + i, is64)], 1);
    }
}

// ============ L2: bnpack (mu finalized inline) | block-scan ============
__global__ void k_bnpack_scan(const float* __restrict__ x, int n, int wb) {
    int bid = blockIdx.x;
    if (bid < wb) {
        __shared__ float smu[256];
        smu[threadIdx.x] = (float)((double)d_musum[threadIdx.x] / (4194304.0 * (double)n));
        __syncthreads();
        int warp = (bid * 256 + threadIdx.x) >> 5;
        int lane = threadIdx.x & 31;
        if (warp >= n) return;
        const float* xr = x + (long long)warp * 256;
#pragma unroll
        for (int w = 0; w < 8; w++) {
            float v = xr[w * 32 + lane];
            unsigned m = __ballot_sync(FULLM, v > smu[w * 32 + lane]);
            if (lane == w) d_bits0[warp * 8 + w] = m;
        }
    } else {
        __shared__ int wsum[8];
        int t = threadIdx.x, lane = t & 31, wrp = t >> 5;
        int chunk = ((n + 255) / 256 + 3) & ~3;
        int c0 = t * chunk, c1 = min(n, c0 + chunk);
        int s = 0, i = c0;
        for (; i + 4 <= c1; i += 4) {
            int4 v = *(const int4*)(d_cnt + i);
            s += v.x + v.y + v.z + v.w;
        }
        for (; i < c1; i++) s += d_cnt[i];
        int incl = s;
        for (int o = 1; o < 32; o <<= 1) {
            int v = __shfl_up_sync(FULLM, incl, o);
            if (lane >= o) incl += v;
        }
        if (lane == 31) wsum[wrp] = incl;
        __syncthreads();
        if (wrp == 0) {
            int v = (lane < 8) ? wsum[lane] : 0;
            for (int o = 1; o < 8; o <<= 1) {
                int u = __shfl_up_sync(FULLM, v, o);
                if (lane >= o) v += u;
            }
            if (lane < 8) wsum[lane] = v;
        }
        __syncthreads();
        int run = incl - s + (wrp ? wsum[wrp - 1] : 0);
        for (i = c0; i < c1; i++) {
            int c = d_cnt[i];
            d_off[i] = run;
            run += c;
            d_dinv[i] = rsqrtf((float)(c + 1));
        }
        if (c0 < n && c1 == n) d_off[n] = run;
    }
}

// bmm body: XOR+popcount -> cnt/2 packed as 4x int8 per word
template <int KW, int OUT, int QOUT, int ROWQ, int NL, int ITER, int CLAMP>
__device__ __forceinline__ void bmm_body8(const unsigned* __restrict__ bits,
                                          const unsigned* __restrict__ wbT,
                                          unsigned* sbits, int blk, int n) {
    const int NPB = NL * ITER;
    int base = blk * NPB;
    int nr = min(NPB, n - base);
    if (nr <= 0) return;
    const int4* src = (const int4*)(bits + (long long)base * KW);
    int nstage = nr * KW / 4;
    for (int i = threadIdx.x; i < nstage; i += blockDim.x)
        ((int4*)sbits)[i] = src[i];
    __syncthreads();
    int t = threadIdx.x;
    if (t >= NL * QOUT) return;
    int q = t % QOUT, nl = t / QOUT, j0 = q * 4;
    unsigned w0[KW], w1[KW], w2[KW], w3[KW];
#pragma unroll
    for (int w = 0; w < KW; w++) {
        w0[w] = wbT[w * OUT + j0];
        w1[w] = wbT[w * OUT + j0 + 1];
        w2[w] = wbT[w * OUT + j0 + 2];
        w3[w] = wbT[w * OUT + j0 + 3];
    }
#pragma unroll 2
    for (int it = 0; it < ITER; it++) {
        int loc = it * NL + nl;
        if (loc >= nr) break;
        int nn = base + loc;
        const unsigned* ab = sbits + loc * KW;
        int p0 = 0, p1 = 0, p2 = 0, p3 = 0;
#pragma unroll
        for (int w = 0; w < KW; w++) {
            unsigned a = ab[w];
            p0 += __popc(a ^ w0[w]);
            p1 += __popc(a ^ w1[w]);
            p2 += __popc(a ^ w2[w]);
            p3 += __popc(a ^ w3[w]);
        }
        int v0 = KW * 16 - p0, v1 = KW * 16 - p1, v2 = KW * 16 - p2, v3 = KW * 16 - p3;
        if (CLAMP) { v0 = min(v0, 127); v1 = min(v1, 127); v2 = min(v2, 127); v3 = min(v3, 127); }
        unsigned pk = (unsigned)(v0 & 0xFF) | ((unsigned)(v1 & 0xFF) << 8) |
                      ((unsigned)(v2 & 0xFF) << 16) | ((unsigned)v3 << 24);
        d_g8[(long long)nn * ROWQ + q] = (int)pk;
    }
}

// ============ L3: bmm layer 0 | CSR fill ============
__global__ void k_bmm0_csr(const void* __restrict__ e, long long E, int n, int bmmb) {
    __shared__ unsigned sbits[64 * 8];
    if ((int)blockIdx.x < bmmb) {
        bmm_body8<8, 128, 32, 32, 8, 8, 1>(d_bits0, d_wb0, sbits, blockIdx.x, n);
    } else {
        int is64 = detect64(e);
        long long i = (long long)(blockIdx.x - bmmb) * blockDim.x + threadIdx.x;
        if (i < E) {
            int sv = ld_edge(e, i, is64);
            int dv = ld_edge(e, E + i, is64);
            int pos = d_off[dv] + atomicAdd(&d_cur[dv], 1);
            d_col[pos] = sv;
        }
    }
}

// ============ L5: bmm layer 1 | re-zero scratch for next call ============
__global__ void k_bmm1_zero(int n, int bmmb) {
    __shared__ unsigned sbits[64 * 4];
    if ((int)blockIdx.x < bmmb) {
        bmm_body8<4, 128, 32, 32, 8, 8, 0>(d_bits1, d_wb1, sbits, blockIdx.x, n);
    } else {
        int b = blockIdx.x - bmmb;
        for (int i = b * 256 + threadIdx.x; i < NMAX; i += 32 * 256) { d_cnt[i] = 0; d_cur[i] = 0; }
        if (b == 0) d_musum[threadIdx.x] = 0;
    }
}

// ============ L7: bmm layer 2 ============
__global__ void k_bmm2(int n) {
    __shared__ unsigned sbits[200 * 4];
    bmm_body8<4, 40, 10, 10, 25, 8, 0>(d_bits2, d_wb2, sbits, blockIdx.x, n);
}

__device__ __forceinline__ void accp(float4& a, int w, float s) {
    a.x += s * (float)__dp4a(w, 1, 0);
    a.y += s * (float)__dp4a(w, 0x100, 0);
    a.z += s * (float)__dp4a(w, 0x10000, 0);
    a.w += s * (float)__dp4a(w, 0x1000000, 0);
}

// ============ aggregation (128 feats, int8 rows) + bias + sign + bitpack ============
template <int OLAYER>
__global__ void k_agg_pack(const float* __restrict__ bias, int n) {
    unsigned* obits = (OLAYER == 1) ? d_bits1 : d_bits2;
    const float* alp = (OLAYER == 1) ? d_al0 : d_al1;
    int wid = (blockIdx.x * blockDim.x + threadIdx.x) >> 5;
    int lane = threadIdx.x & 31;
    if (wid >= n) return;
    float di = d_dinv[wid];
    float4 A = make_float4(0.f, 0.f, 0.f, 0.f), B = A;
    accp(A, d_g8[(long long)wid * 32 + lane], di);      // self loop
    int k = d_off[wid], k1 = d_off[wid + 1];
    for (; k + 8 <= k1; k += 8) {
        int c[8]; float s[8]; int w[8];
#pragma unroll
        for (int j = 0; j < 8; j++) c[j] = d_col[k + j];
#pragma unroll
        for (int j = 0; j < 8; j++) s[j] = d_dinv[c[j]];
#pragma unroll
        for (int j = 0; j < 8; j++) w[j] = d_g8[(long long)c[j] * 32 + lane];
#pragma unroll
        for (int j = 0; j < 8; j++) accp((j & 1) ? B : A, w[j], s[j]);
    }
    if (k + 4 <= k1) {
        int c[4]; float s[4]; int w[4];
#pragma unroll
        for (int j = 0; j < 4; j++) c[j] = d_col[k + j];
#pragma unroll
        for (int j = 0; j < 4; j++) s[j] = d_dinv[c[j]];
#pragma unroll
        for (int j = 0; j < 4; j++) w[j] = d_g8[(long long)c[j] * 32 + lane];
#pragma unroll
        for (int j = 0; j < 4; j++) accp((j & 1) ? B : A, w[j], s[j]);
        k += 4;
    }
    for (; k < k1; k++) {
        int c = d_col[k];
        accp(B, d_g8[(long long)c * 32 + lane], d_dinv[c]);
    }
    float4 al = ((const float4*)alp)[lane];
    float4 b  = ((const float4*)bias)[lane];
    float d2 = 2.f * di;                       // undo cnt/2 storage
    float v0 = (A.x + B.x) * al.x * d2 + b.x;
    float v1 = (A.y + B.y) * al.y * d2 + b.y;
    float v2 = (A.z + B.z) * al.z * d2 + b.z;
    float v3 = (A.w + B.w) * al.w * d2 + b.w;
    unsigned nib = (unsigned)(v0 > 0.f) | ((unsigned)(v1 > 0.f) << 1) |
                   ((unsigned)(v2 > 0.f) << 2) | ((unsigned)(v3 > 0.f) << 3);
    unsigned sh = nib << ((lane & 7) * 4);
    sh |= __shfl_xor_sync(FULLM, sh, 1);
    sh |= __shfl_xor_sync(FULLM, sh, 2);
    sh |= __shfl_xor_sync(FULLM, sh, 4);
    if ((lane & 7) == 0) obits[wid * 4 + (lane >> 3)] = sh;
}

// ============ final aggregation (40 feats, int8 rows) + bias + log_softmax ============
__global__ void k_agg_out(const float* __restrict__ bias, float* __restrict__ out, int n) {
    int wid = (blockIdx.x * blockDim.x + threadIdx.x) >> 5;
    int lane = threadIdx.x & 31;
    if (wid >= n) return;
    bool act = lane < 10;
    float di = d_dinv[wid];
    float4 A = make_float4(0.f, 0.f, 0.f, 0.f), B = A;
    if (act) accp(A, d_g8[(long long)wid * 10 + lane], di);
    int k = d_off[wid], k1 = d_off[wid + 1];
    for (; k + 8 <= k1; k += 8) {
        int c[8]; float s[8]; int w[8];
#pragma unroll
        for (int j = 0; j < 8; j++) c[j] = d_col[k + j];
#pragma unroll
        for (int j = 0; j < 8; j++) s[j] = d_dinv[c[j]];
        if (act) {
#pragma unroll
            for (int j = 0; j < 8; j++) w[j] = d_g8[(long long)c[j] * 10 + lane];
#pragma unroll
            for (int j = 0; j < 8; j++) accp((j & 1) ? B : A, w[j], s[j]);
        }
    }
    for (; k < k1; k++) {
        int c = d_col[k];
        float s = d_dinv[c];
        if (act) accp(B, d_g8[(long long)c * 10 + lane], s);
    }
    float4 v = make_float4(-1e30f, -1e30f, -1e30f, -1e30f);
    if (act) {
        float4 al = ((const float4*)d_al2)[lane];
        float4 b  = ((const float4*)bias)[lane];
        float d2 = 2.f * di;
        v.x = (A.x + B.x) * al.x * d2 + b.x;
        v.y = (A.y + B.y) * al.y * d2 + b.y;
        v.z = (A.z + B.z) * al.z * d2 + b.z;
        v.w = (A.w + B.w) * al.w * d2 + b.w;
    }
    float m = fmaxf(fmaxf(v.x, v.y), fmaxf(v.z, v.w));
    for (int o = 16; o; o >>= 1) m = fmaxf(m, __shfl_xor_sync(FULLM, m, o));
    float se = act ? (expf(v.x - m) + expf(v.y - m) + expf(v.z - m) + expf(v.w - m)) : 0.f;
    for (int o = 16; o; o >>= 1) se += __shfl_xor_sync(FULLM, se, o);
    float lse = logf(se) + m;
    if (act) {
        v.x -= lse; v.y -= lse; v.z -= lse; v.w -= lse;
        ((float4*)out)[(long long)wid * 10 + lane] = v;
    }
}

// ---------------- launch ----------------
extern "C" void kernel_launch(void* const* d_in, const int* in_sizes, int n_in,
                              void* d_out, int out_size) {
    const float* x  = (const float*)d_in[0];
    const void*  ei = d_in[1];
    const float* W0 = (const float*)d_in[2];
    const float* b0 = (const float*)d_in[3];
    const float* W1 = (const float*)d_in[4];
    const float* b1 = (const float*)d_in[5];
    const float* W2 = (const float*)d_in[6];
    const float* b2 = (const float*)d_in[7];
    float* out = (float*)d_out;

    int N = in_sizes[0] / 256;
    long long E = (long long)in_sizes[1] / 2;

    int eb = (int)((E + 255) / 256);
    int wb = (N + 7) / 8;
    int bmmb = (N + 63) / 64;

    k_prep<<<549 + eb, 256>>>(x, W0, W1, W2, ei, E, N);          // 1: colsum|wprep|deg
    k_bnpack_scan<<<wb + 1, 256>>>(x, N, wb);                    // 2: bits0|scan
    k_bmm0_csr<<<bmmb + eb, 256>>>(ei, E, N, bmmb);              // 3: bmm0|csr
    k_agg_pack<1><<<wb, 256>>>(b0, N);                           // 4: agg L0 (PROFILED)
    k_bmm1_zero<<<bmmb + 32, 256>>>(N, bmmb);                    // 5: bmm1|re-zero
    k_agg_pack<2><<<wb, 256>>>(b1, N);                           // 6: agg L1
    k_bmm2<<<(N + 199) / 200, 256>>>(N);                         // 7: bmm2
    k_agg_out<<<wb, 256>>>(b2, out, N);                          // 8: agg out + softmax
}

// round 7
// speedup vs baseline: 1.2957x; 1.2957x over previous
#include <cuda_runtime.h>
#include <cuda_fp16.h>
#include <math.h>

#define FULLM 0xffffffffu
static const int NMAX = 100352;
static const int EMAX = 1700000;

// ---------------- device scratch ----------------
__device__ long long d_musum[256];
__device__ int      d_cnt[NMAX];
__device__ int      d_cur[NMAX];
__device__ int      d_off[NMAX + 1];
__device__ float    d_dinv[NMAX];
__device__ int      d_col[EMAX];
__device__ uint2    d_ga[NMAX * 32];   // layer-0 cnt (fp16 exact), rows of 32 uint2
__device__ uint2    d_gb[NMAX * 32];   // layer-1 cnt
__device__ uint2    d_g2[NMAX * 10];   // layer-2 cnt (40 feats)
__device__ __align__(16) unsigned d_wb0[8 * 128];
__device__ __align__(16) unsigned d_wb1[4 * 128];
__device__ __align__(16) unsigned d_wb2[4 * 40];
__device__ __align__(16) float d_al0[128];
__device__ __align__(16) float d_al1[128];
__device__ __align__(16) float d_al2[40];

__device__ __forceinline__ int detect64(const void* e) {
    const unsigned* w = (const unsigned*)e;
    int lane = threadIdx.x & 31;
    unsigned h0 = w[2 * lane + 1];
    unsigned h1 = w[64 + 2 * lane + 1];
    int z = __popc(__ballot_sync(FULLM, h0 == 0)) + __popc(__ballot_sync(FULLM, h1 == 0));
    return z >= 32;
}
__device__ __forceinline__ int ld_edge(const void* e, long long idx, int is64) {
    return is64 ? (int)((const long long*)e)[idx] : ((const int*)e)[idx];
}

// ============ L1: colsum partial | wprep | degree histogram ============
__global__ void k_prep(const float* __restrict__ x,
                       const float* __restrict__ W0,
                       const float* __restrict__ W1,
                       const float* __restrict__ W2,
                       const void* __restrict__ e, long long E, int n) {
    int bid = blockIdx.x;
    if (bid < 512) {
        int rows = (n + 511) / 512;
        int r0 = bid * rows, r1 = min(n, r0 + rows);
        float s = 0.f;
        for (int r = r0; r < r1; r++) s += x[(long long)r * 256 + threadIdx.x];
        long long q = llrintf(s * 4194304.f);
        atomicAdd((unsigned long long*)&d_musum[threadIdx.x], (unsigned long long)q);
    } else if (bid < 549) {
        int W = (bid - 512) * 8 + (threadIdx.x >> 5);
        int lane = threadIdx.x & 31;
        const float* Wsrc; unsigned* wbT; float* alpha; int K, OUT, j;
        if (W < 128)      { Wsrc = W0; wbT = d_wb0; alpha = d_al0; K = 256; OUT = 128; j = W; }
        else if (W < 256) { Wsrc = W1; wbT = d_wb1; alpha = d_al1; K = 128; OUT = 128; j = W - 128; }
        else if (W < 296) { Wsrc = W2; wbT = d_wb2; alpha = d_al2; K = 128; OUT = 40;  j = W - 256; }
        else return;
        float s = 0.f;
        int KW = K / 32;
        for (int w = 0; w < KW; w++) {
            float v = Wsrc[(long long)(w * 32 + lane) * OUT + j];
            s += fabsf(v);
            unsigned m = __ballot_sync(FULLM, v > 0.f);
            if (lane == 0) wbT[w * OUT + j] = m;
        }
        for (int o = 16; o; o >>= 1) s += __shfl_xor_sync(FULLM, s, o);
        if (lane == 0) alpha[j] = s / (float)K;
    } else {
        int is64 = detect64(e);
        long long i = (long long)(bid - 549) * blockDim.x + threadIdx.x;
        if (i < E) atomicAdd(&d_cnt[ld_edge(e, E + i, is64)], 1);
    }
}

// ============ L2: fused bnpack + bmm0 (bits stay in regs) | block-scan ============
__global__ void k_bnpack_bmm0_scan(const float* __restrict__ x, int n, int wb64) {
    int bid = blockIdx.x;
    if (bid < wb64) {
        __shared__ float smu[256];
        smu[threadIdx.x] = (float)((double)d_musum[threadIdx.x] / (4194304.0 * (double)n));
        __syncthreads();
        int warp = threadIdx.x >> 5, lane = threadIdx.x & 31;
        uint4 wv[8];
#pragma unroll
        for (int w = 0; w < 8; w++) wv[w] = *(const uint4*)&d_wb0[w * 128 + 4 * lane];
        int n0 = bid * 64 + warp * 8;
#pragma unroll
        for (int i = 0; i < 8; i++) {
            int node = n0 + i;
            if (node >= n) break;
            const float* xr = x + (long long)node * 256;
            unsigned bw[8];
#pragma unroll
            for (int w = 0; w < 8; w++) {
                float v = xr[w * 32 + lane];
                bw[w] = __ballot_sync(FULLM, v > smu[w * 32 + lane]);
            }
            int p0 = 0, p1 = 0, p2 = 0, p3 = 0;
#pragma unroll
            for (int w = 0; w < 8; w++) {
                p0 += __popc(bw[w] ^ wv[w].x);
                p1 += __popc(bw[w] ^ wv[w].y);
                p2 += __popc(bw[w] ^ wv[w].z);
                p3 += __popc(bw[w] ^ wv[w].w);
            }
            __half2 h0 = __floats2half2_rn((float)(256 - 2 * p0), (float)(256 - 2 * p1));
            __half2 h1 = __floats2half2_rn((float)(256 - 2 * p2), (float)(256 - 2 * p3));
            uint2 u;
            u.x = *(unsigned*)&h0;
            u.y = *(unsigned*)&h1;
            d_ga[(long long)node * 32 + lane] = u;
        }
    } else {
        __shared__ int wsum[8];
        int t = threadIdx.x, lane = t & 31, wrp = t >> 5;
        int chunk = ((n + 255) / 256 + 3) & ~3;
        int c0 = t * chunk, c1 = min(n, c0 + chunk);
        int s = 0, i = c0;
        for (; i + 4 <= c1; i += 4) {
            int4 v = *(const int4*)(d_cnt + i);
            s += v.x + v.y + v.z + v.w;
        }
        for (; i < c1; i++) s += d_cnt[i];
        int incl = s;
        for (int o = 1; o < 32; o <<= 1) {
            int v = __shfl_up_sync(FULLM, incl, o);
            if (lane >= o) incl += v;
        }
        if (lane == 31) wsum[wrp] = incl;
        __syncthreads();
        if (wrp == 0) {
            int v = (lane < 8) ? wsum[lane] : 0;
            for (int o = 1; o < 8; o <<= 1) {
                int u = __shfl_up_sync(FULLM, v, o);
                if (lane >= o) v += u;
            }
            if (lane < 8) wsum[lane] = v;
        }
        __syncthreads();
        int run = incl - s + (wrp ? wsum[wrp - 1] : 0);
        for (i = c0; i < c1; i++) {
            int c = d_cnt[i];
            d_off[i] = run;
            run += c;
            d_dinv[i] = rsqrtf((float)(c + 1));
        }
        if (c0 < n && c1 == n) d_off[n] = run;
    }
}

// ============ L3: CSR fill ============
__global__ void k_csr(const void* __restrict__ e, long long E) {
    int is64 = detect64(e);
    long long i = (long long)blockIdx.x * blockDim.x + threadIdx.x;
    if (i < E) {
        int sv = ld_edge(e, i, is64);
        int dv = ld_edge(e, E + i, is64);
        int pos = d_off[dv] + atomicAdd(&d_cur[dv], 1);
        d_col[pos] = sv;
    }
}

__device__ __forceinline__ void accH(float4& a, uint2 u, float s) {
    float2 f0 = __half22float2(*reinterpret_cast<__half2*>(&u.x));
    float2 f1 = __half22float2(*reinterpret_cast<__half2*>(&u.y));
    a.x += s * f0.x; a.y += s * f0.y; a.z += s * f1.x; a.w += s * f1.y;
}

// gather body over CSR: returns A+B accumulated dinv[s]*cnt[s]
__device__ __forceinline__ float4 gather128(const uint2* __restrict__ gp, int wid, int lane) {
    float4 A = make_float4(0.f, 0.f, 0.f, 0.f), B = A;
    accH(A, gp[(long long)wid * 32 + lane], d_dinv[wid]);   // self loop
    int k = d_off[wid], k1 = d_off[wid + 1];
    for (; k + 8 <= k1; k += 8) {
        int c[8]; float s[8]; uint2 u[8];
#pragma unroll
        for (int j = 0; j < 8; j++) c[j] = d_col[k + j];
#pragma unroll
        for (int j = 0; j < 8; j++) s[j] = d_dinv[c[j]];
#pragma unroll
        for (int j = 0; j < 8; j++) u[j] = gp[(long long)c[j] * 32 + lane];
#pragma unroll
        for (int j = 0; j < 8; j++) accH((j & 1) ? B : A, u[j], s[j]);
    }
    if (k + 4 <= k1) {
        int c[4]; float s[4]; uint2 u[4];
#pragma unroll
        for (int j = 0; j < 4; j++) c[j] = d_col[k + j];
#pragma unroll
        for (int j = 0; j < 4; j++) s[j] = d_dinv[c[j]];
#pragma unroll
        for (int j = 0; j < 4; j++) u[j] = gp[(long long)c[j] * 32 + lane];
#pragma unroll
        for (int j = 0; j < 4; j++) accH((j & 1) ? B : A, u[j], s[j]);
        k += 4;
    }
    for (; k < k1; k++) {
        int c = d_col[k];
        accH(B, gp[(long long)c * 32 + lane], d_dinv[c]);
    }
    A.x += B.x; A.y += B.y; A.z += B.z; A.w += B.w;
    return A;
}

// epilogue: v -> sign nibble -> 4 broadcast bit-words
__device__ __forceinline__ void sign_words(float v0, float v1, float v2, float v3,
                                           int lane, unsigned bw[4]) {
    unsigned nib = (unsigned)(v0 > 0.f) | ((unsigned)(v1 > 0.f) << 1) |
                   ((unsigned)(v2 > 0.f) << 2) | ((unsigned)(v3 > 0.f) << 3);
    unsigned sh = nib << ((lane & 7) * 4);
    sh |= __shfl_xor_sync(FULLM, sh, 1);
    sh |= __shfl_xor_sync(FULLM, sh, 2);
    sh |= __shfl_xor_sync(FULLM, sh, 4);
#pragma unroll
    for (int wd = 0; wd < 4; wd++) bw[wd] = __shfl_sync(FULLM, sh, wd * 8);
}

// ============ L4: fused agg(layer-0 g) + sign + bmm1 -> d_gb ============
__global__ void k_agg1_bmm1(const float* __restrict__ bias, int n) {
    int wid = (blockIdx.x * blockDim.x + threadIdx.x) >> 5;
    int lane = threadIdx.x & 31;
    if (wid >= n) return;
    float4 A = gather128(d_ga, wid, lane);
    float di = d_dinv[wid];
    float4 al = ((const float4*)d_al0)[lane];
    float4 b  = ((const float4*)bias)[lane];
    float v0 = A.x * al.x * di + b.x;
    float v1 = A.y * al.y * di + b.y;
    float v2 = A.z * al.z * di + b.z;
    float v3 = A.w * al.w * di + b.w;
    unsigned bw[4];
    sign_words(v0, v1, v2, v3, lane, bw);
    uint4 wv[4];
#pragma unroll
    for (int w = 0; w < 4; w++) wv[w] = *(const uint4*)&d_wb1[w * 128 + 4 * lane];
    int p0 = 0, p1 = 0, p2 = 0, p3 = 0;
#pragma unroll
    for (int w = 0; w < 4; w++) {
        p0 += __popc(bw[w] ^ wv[w].x);
        p1 += __popc(bw[w] ^ wv[w].y);
        p2 += __popc(bw[w] ^ wv[w].z);
        p3 += __popc(bw[w] ^ wv[w].w);
    }
    __half2 h0 = __floats2half2_rn((float)(128 - 2 * p0), (float)(128 - 2 * p1));
    __half2 h1 = __floats2half2_rn((float)(128 - 2 * p2), (float)(128 - 2 * p3));
    uint2 u;
    u.x = *(unsigned*)&h0;
    u.y = *(unsigned*)&h1;
    d_gb[(long long)wid * 32 + lane] = u;
}

// ============ L5: fused agg(layer-1 g) + sign + bmm2 -> d_g2 | re-zero scratch ============
__global__ void k_agg2_bmm2(const float* __restrict__ bias, int n, int wpb) {
    if ((int)blockIdx.x >= wpb) {
        int b = blockIdx.x - wpb;
        for (int i = b * 256 + threadIdx.x; i < NMAX; i += 16 * 256) { d_cnt[i] = 0; d_cur[i] = 0; }
        if (b == 0 && threadIdx.x < 256) d_musum[threadIdx.x] = 0;
        return;
    }
    int wid = (blockIdx.x * blockDim.x + threadIdx.x) >> 5;
    int lane = threadIdx.x & 31;
    if (wid >= n) return;
    float4 A = gather128(d_gb, wid, lane);
    float di = d_dinv[wid];
    float4 al = ((const float4*)d_al1)[lane];
    float4 b  = ((const float4*)bias)[lane];
    float v0 = A.x * al.x * di + b.x;
    float v1 = A.y * al.y * di + b.y;
    float v2 = A.z * al.z * di + b.z;
    float v3 = A.w * al.w * di + b.w;
    unsigned bw[4];
    sign_words(v0, v1, v2, v3, lane, bw);
    if (lane < 10) {
        uint4 wv[4];
#pragma unroll
        for (int w = 0; w < 4; w++) wv[w] = *(const uint4*)&d_wb2[w * 40 + 4 * lane];
        int p0 = 0, p1 = 0, p2 = 0, p3 = 0;
#pragma unroll
        for (int w = 0; w < 4; w++) {
            p0 += __popc(bw[w] ^ wv[w].x);
            p1 += __popc(bw[w] ^ wv[w].y);
            p2 += __popc(bw[w] ^ wv[w].z);
            p3 += __popc(bw[w] ^ wv[w].w);
        }
        __half2 h0 = __floats2half2_rn((float)(128 - 2 * p0), (float)(128 - 2 * p1));
        __half2 h1 = __floats2half2_rn((float)(128 - 2 * p2), (float)(128 - 2 * p3));
        uint2 u;
        u.x = *(unsigned*)&h0;
        u.y = *(unsigned*)&h1;
        d_g2[(long long)wid * 10 + lane] = u;
    }
}

// ============ L6: final aggregation (40 feats) + bias + log_softmax ============
__global__ void k_agg_out(const float* __restrict__ bias, float* __restrict__ out, int n) {
    int wid = (blockIdx.x * blockDim.x + threadIdx.x) >> 5;
    int lane = threadIdx.x & 31;
    if (wid >= n) return;
    const __half2* gh = (const __half2*)d_g2;
    bool act = lane < 20;
    float di = d_dinv[wid];
    float2 A = make_float2(0.f, 0.f), B = A;
    if (act) {
        float2 f = __half22float2(gh[(long long)wid * 20 + lane]);
        A.x += di * f.x; A.y += di * f.y;
    }
    int k = d_off[wid], k1 = d_off[wid + 1];
    for (; k + 8 <= k1; k += 8) {
        int c[8]; float s[8]; float2 f[8];
#pragma unroll
        for (int j = 0; j < 8; j++) c[j] = d_col[k + j];
#pragma unroll
        for (int j = 0; j < 8; j++) s[j] = d_dinv[c[j]];
        if (act) {
#pragma unroll
            for (int j = 0; j < 8; j++) f[j] = __half22float2(gh[(long long)c[j] * 20 + lane]);
#pragma unroll
            for (int j = 0; j < 8; j++) {
                if (j & 1) { B.x += s[j] * f[j].x; B.y += s[j] * f[j].y; }
                else       { A.x += s[j] * f[j].x; A.y += s[j] * f[j].y; }
            }
        }
    }
    for (; k < k1; k++) {
        int c = d_col[k];
        float s = d_dinv[c];
        if (act) {
            float2 f = __half22float2(gh[(long long)c * 20 + lane]);
            B.x += s * f.x; B.y += s * f.y;
        }
    }
    float v0 = -1e30f, v1 = -1e30f;
    if (act) {
        float2 al = ((const float2*)d_al2)[lane];
        float2 b  = ((const float2*)bias)[lane];
        v0 = (A.x + B.x) * al.x * di + b.x;
        v1 = (A.y + B.y) * al.y * di + b.y;
    }
    float m = fmaxf(v0, v1);
    for (int o = 16; o; o >>= 1) m = fmaxf(m, __shfl_xor_sync(FULLM, m, o));
    float se = act ? (expf(v0 - m) + expf(v1 - m)) : 0.f;
    for (int o = 16; o; o >>= 1) se += __shfl_xor_sync(FULLM, se, o);
    float lse = logf(se);
    if (act) {
        float2 r;
        r.x = v0 - m - lse;
        r.y = v1 - m - lse;
        ((float2*)out)[(long long)wid * 20 + lane] = r;
    }
}

// ---------------- launch ----------------
extern "C" void kernel_launch(void* const* d_in, const int* in_sizes, int n_in,
                              void* d_out, int out_size) {
    const float* x  = (const float*)d_in[0];
    const void*  ei = d_in[1];
    const float* W0 = (const float*)d_in[2];
    const float* b0 = (const float*)d_in[3];
    const float* W1 = (const float*)d_in[4];
    const float* b1 = (const float*)d_in[5];
    const float* W2 = (const float*)d_in[6];
    const float* b2 = (const float*)d_in[7];
    float* out = (float*)d_out;

    int N = in_sizes[0] / 256;
    long long E = (long long)in_sizes[1] / 2;

    int eb   = (int)((E + 255) / 256);
    int wb64 = (N + 63) / 64;
    int wpb  = (N + 7) / 8;

    k_prep<<<549 + eb, 256>>>(x, W0, W1, W2, ei, E, N);     // 1: colsum|wprep|deg
    k_bnpack_bmm0_scan<<<wb64 + 1, 256>>>(x, N, wb64);      // 2: bn+sign+bmm0|scan
    k_csr<<<eb, 256>>>(ei, E);                              // 3: csr fill
    k_agg1_bmm1<<<wpb, 256>>>(b0, N);                       // 4: agg+bmm1 (PROFILED)
    k_agg2_bmm2<<<wpb + 16, 256>>>(b1, N, wpb);             // 5: agg+bmm2|re-zero
    k_agg_out<<<wpb, 256>>>(b2, out, N);                    // 6: agg+softmax
}